// round 9
// baseline (speedup 1.0000x reference)
#include <cuda_runtime.h>

// SAGE_69587060130174 — MaxK-GNN forward on GB300 (sm_103a), fp32 SIMT.
//
// Fully fused pipeline (top-32 in GEMM epilogues; lin_out in layer-1 epilogue;
// no dense h ever hits DRAM):
//   deg = out-degree(src)                          (memset + atomicAdd)
//   pack = top32(x @ W_in + b_in)                  (GEMM + in-register REDUX.MAX)
//   l=0: agg[s] += sparse(pack[d]) over edges      (32 atomicAdds per edge)
//        pack = top32(sparse @ W_self0 + (agg/deg) @ W_neigh0)
//   l=1: agg[s] += sparse(pack[d]) over edges
//        out = (sparse @ W_self1 + (agg/deg) @ W_neigh1) @ W_out + b_out
//              (second GEMM fused via SMEM tile, bit-identical to 2-kernel path)

static constexpr int NNODES = 50000;
static constexpr int NEDGES = 800000;
static constexpr int HIDDIM = 128;
static constexpr int OUTDIM = 64;
static constexpr int KTOP   = 32;

// ---- scratch (static device globals; no allocation allowed) ----
__device__ float  g_agg[(size_t)NNODES * HIDDIM];   // 25.6 MB
__device__ float2 g_pack[(size_t)NNODES * KTOP];    // 12.8 MB  (.x=val, .y=idx bits)
__device__ float  g_deg[NNODES];

// ---------------------------------------------------------------------------
// Exact, stable top-32 of a warp-held 128-vector (lane holds cols lane*4+q).
// 32 rounds of warp argmax via monotonic-key REDUX.MAX; tie-break = smallest
// column index (strict '>' in the per-lane scan, lowest-set-lane ballot) —
// matches jax.lax.top_k ordering semantics. Writes float2{val, idx_bits}.
__device__ __forceinline__ void warp_top32(float m0, float m1, float m2, float m3,
                                           int lane, float2* __restrict__ dst) {
    const float NEG = __int_as_float(0xff800000);  // -inf
    for (int t = 0; t < 32; t++) {
        float lm = m0; int lq = 0;
        if (m1 > lm) { lm = m1; lq = 1; }
        if (m2 > lm) { lm = m2; lq = 2; }
        if (m3 > lm) { lm = m3; lq = 3; }
        unsigned key = __float_as_uint(lm);
        key = (key & 0x80000000u) ? ~key : (key | 0x80000000u);
        unsigned wk   = __reduce_max_sync(0xffffffffu, key);
        unsigned ball = __ballot_sync(0xffffffffu, key == wk);
        int srcl = __ffs(ball) - 1;
        float wv = __shfl_sync(0xffffffffu, lm, srcl);
        int   wq = __shfl_sync(0xffffffffu, lq, srcl);
        if (lane == srcl) {
            if      (lq == 0) m0 = NEG;
            else if (lq == 1) m1 = NEG;
            else if (lq == 2) m2 = NEG;
            else              m3 = NEG;
        }
        if (lane == t)
            dst[t] = make_float2(wv, __int_as_float((srcl << 2) | wq));
    }
}

// ---------------------------------------------------------------------------
__global__ void k_deg(const int* __restrict__ ei) {
    int stride = gridDim.x * blockDim.x;
    for (int e = blockIdx.x * blockDim.x + threadIdx.x; e < NEDGES; e += stride)
        atomicAdd(&g_deg[__ldg(ei + e)], 1.0f);
}

// ---------------------------------------------------------------------------
// lin_in + fused top32: pack = top32(A[N,128] @ W[128,128] + bias).
// W cached in SMEM; each warp computes 4 rows via a per-warp transposed A-tile.
__global__ __launch_bounds__(512) void k_lin_in(const float* __restrict__ A,
                                                const float* __restrict__ W,
                                                const float* __restrict__ bias,
                                                int N) {
    extern __shared__ float sm[];
    float* sW = sm;                  // 16384 floats
    float* sA = sm + 16384;          // nwarp * 512 floats (A^T tile: [128][4])

    const int tid  = threadIdx.x;
    const int warp = tid >> 5, lane = tid & 31;
    const int nwarp = blockDim.x >> 5;

    for (int i = tid; i < 4096; i += blockDim.x)
        reinterpret_cast<float4*>(sW)[i] = reinterpret_cast<const float4*>(W)[i];
    __syncthreads();

    const int base = blockIdx.x * nwarp * 4 + warp * 4;
    float* myA = sA + warp * 512;

    #pragma unroll
    for (int r = 0; r < 4; r++) {
        int row = base + r;
        float4 av = make_float4(0.f, 0.f, 0.f, 0.f);
        if (row < N)
            av = reinterpret_cast<const float4*>(A + (size_t)row * 128)[lane];
        myA[(lane * 4 + 0) * 4 + r] = av.x;
        myA[(lane * 4 + 1) * 4 + r] = av.y;
        myA[(lane * 4 + 2) * 4 + r] = av.z;
        myA[(lane * 4 + 3) * 4 + r] = av.w;
    }
    __syncwarp();

    float acc[4][4];
    #pragma unroll
    for (int q = 0; q < 4; q++) {
        float bv = bias[lane * 4 + q];
        #pragma unroll
        for (int r = 0; r < 4; r++) acc[r][q] = bv;
    }

    #pragma unroll 4
    for (int kk = 0; kk < 128; kk++) {
        float4 a4 = reinterpret_cast<float4*>(myA)[kk];
        float4 w = *reinterpret_cast<const float4*>(&sW[kk * 128 + lane * 4]);
        acc[0][0] += a4.x * w.x; acc[0][1] += a4.x * w.y; acc[0][2] += a4.x * w.z; acc[0][3] += a4.x * w.w;
        acc[1][0] += a4.y * w.x; acc[1][1] += a4.y * w.y; acc[1][2] += a4.y * w.z; acc[1][3] += a4.y * w.w;
        acc[2][0] += a4.z * w.x; acc[2][1] += a4.z * w.y; acc[2][2] += a4.z * w.z; acc[2][3] += a4.z * w.w;
        acc[3][0] += a4.w * w.x; acc[3][1] += a4.w * w.y; acc[3][2] += a4.w * w.z; acc[3][3] += a4.w * w.w;
    }

    #pragma unroll
    for (int r = 0; r < 4; r++) {
        int row = base + r;
        if (row < N)  // warp-uniform branch
            warp_top32(acc[r][0], acc[r][1], acc[r][2], acc[r][3],
                       lane, g_pack + (size_t)row * KTOP);
    }
}

// ---------------------------------------------------------------------------
// Edge scatter: one warp per edge; each lane handles one of the 32 nonzeros of
// hs[dst] (single coalesced float2 load) and atomically adds into agg[src].
__global__ __launch_bounds__(256) void k_scatter(const int* __restrict__ ei) {
    int gw = (blockIdx.x * blockDim.x + threadIdx.x) >> 5;
    if (gw >= NEDGES) return;
    int lane = threadIdx.x & 31;
    int s = __ldg(ei + gw);
    int d = __ldg(ei + NEDGES + gw);
    float2 p = g_pack[(size_t)d * KTOP + lane];
    float* ap = g_agg + (size_t)s * 128;
    atomicAdd(ap + __float_as_int(p.y), p.x);
}

// ---------------------------------------------------------------------------
// Fused layer: t = sparse(pack) @ W_self + (agg/(deg+1e-6)) @ W_neigh.
// MODE 0: pack = top32(t)         (feeds next layer)
// MODE 1: out  = t @ W_out + b_out (lin_out fused through the SMEM A-tile,
//         bit-identical to storing t and re-running the dense GEMM)
template <int MODE>
__global__ __launch_bounds__(512) void k_layer(const float* __restrict__ Ws,
                                               const float* __restrict__ Wn,
                                               const float* __restrict__ Wo,
                                               const float* __restrict__ bo,
                                               float* __restrict__ out) {
    extern __shared__ float sm[];
    float* sWs = sm;                                   // 16384 floats
    float* sWn = sm + 16384;                           // 16384 floats
    float* sWo = sm + 32768;                           // 8192 floats (MODE 1)
    float* sA  = sm + (MODE ? 40960 : 32768);          // nwarp * 512 floats

    const int tid  = threadIdx.x;
    const int warp = tid >> 5, lane = tid & 31;
    const int nwarp = blockDim.x >> 5;

    for (int i = tid; i < 4096; i += blockDim.x) {
        reinterpret_cast<float4*>(sWs)[i] = reinterpret_cast<const float4*>(Ws)[i];
        reinterpret_cast<float4*>(sWn)[i] = reinterpret_cast<const float4*>(Wn)[i];
    }
    if constexpr (MODE == 1) {
        for (int i = tid; i < 2048; i += blockDim.x)
            reinterpret_cast<float4*>(sWo)[i] = reinterpret_cast<const float4*>(Wo)[i];
    }
    __syncthreads();

    const int base = blockIdx.x * nwarp * 4 + warp * 4;
    float* myA = sA + warp * 512;

    float sval[4]; int sidx[4];
    #pragma unroll
    for (int r = 0; r < 4; r++) {
        int row = base + r;
        if (row < NNODES) {
            float inv = 1.0f / (g_deg[row] + 1e-6f);
            float4 a = reinterpret_cast<const float4*>(g_agg + (size_t)row * 128)[lane];
            myA[(lane * 4 + 0) * 4 + r] = a.x * inv;
            myA[(lane * 4 + 1) * 4 + r] = a.y * inv;
            myA[(lane * 4 + 2) * 4 + r] = a.z * inv;
            myA[(lane * 4 + 3) * 4 + r] = a.w * inv;
            float2 p = g_pack[(size_t)row * KTOP + lane];
            sval[r] = p.x;
            sidx[r] = __float_as_int(p.y);
        } else {
            myA[(lane * 4 + 0) * 4 + r] = 0.f;
            myA[(lane * 4 + 1) * 4 + r] = 0.f;
            myA[(lane * 4 + 2) * 4 + r] = 0.f;
            myA[(lane * 4 + 3) * 4 + r] = 0.f;
            sval[r] = 0.f; sidx[r] = 0;
        }
    }
    __syncwarp();

    float acc[4][4] = {};

    // sparse self-term: 32 nonzeros, broadcast (val, idx) from the owning lane
    #pragma unroll 8
    for (int t = 0; t < 32; t++) {
        #pragma unroll
        for (int r = 0; r < 4; r++) {
            float v = __shfl_sync(0xffffffffu, sval[r], t);
            int   j = __shfl_sync(0xffffffffu, sidx[r], t);
            float4 w = *reinterpret_cast<const float4*>(&sWs[j * 128 + lane * 4]);
            acc[r][0] += v * w.x; acc[r][1] += v * w.y;
            acc[r][2] += v * w.z; acc[r][3] += v * w.w;
        }
    }

    // dense neighbor term
    #pragma unroll 4
    for (int kk = 0; kk < 128; kk++) {
        float4 a = reinterpret_cast<float4*>(myA)[kk];
        float4 w = *reinterpret_cast<const float4*>(&sWn[kk * 128 + lane * 4]);
        acc[0][0] += a.x * w.x; acc[0][1] += a.x * w.y; acc[0][2] += a.x * w.z; acc[0][3] += a.x * w.w;
        acc[1][0] += a.y * w.x; acc[1][1] += a.y * w.y; acc[1][2] += a.y * w.z; acc[1][3] += a.y * w.w;
        acc[2][0] += a.z * w.x; acc[2][1] += a.z * w.y; acc[2][2] += a.z * w.z; acc[2][3] += a.z * w.w;
        acc[3][0] += a.w * w.x; acc[3][1] += a.w * w.y; acc[3][2] += a.w * w.z; acc[3][3] += a.w * w.w;
    }

    if constexpr (MODE == 0) {
        #pragma unroll
        for (int r = 0; r < 4; r++) {
            int row = base + r;
            if (row < NNODES)  // warp-uniform branch
                warp_top32(acc[r][0], acc[r][1], acc[r][2], acc[r][3],
                           lane, g_pack + (size_t)row * KTOP);
        }
    } else {
        // Fused lin_out: re-stage acc into the transposed A-tile layout (the
        // exact store pattern of the dense-GEMM loader), then the identical
        // CPL=2 inner loop against sWo. Bit-identical to the 2-kernel path.
        #pragma unroll
        for (int r = 0; r < 4; r++) {
            #pragma unroll
            for (int q = 0; q < 4; q++)
                myA[(lane * 4 + q) * 4 + r] = acc[r][q];
        }
        __syncwarp();

        float acc2[4][2];
        #pragma unroll
        for (int q = 0; q < 2; q++) {
            float bv = bo[lane * 2 + q];
            #pragma unroll
            for (int r = 0; r < 4; r++) acc2[r][q] = bv;
        }

        #pragma unroll 4
        for (int kk = 0; kk < 128; kk++) {
            float4 a4 = reinterpret_cast<float4*>(myA)[kk];
            float2 w = *reinterpret_cast<const float2*>(&sWo[kk * 64 + lane * 2]);
            acc2[0][0] += a4.x * w.x; acc2[0][1] += a4.x * w.y;
            acc2[1][0] += a4.y * w.x; acc2[1][1] += a4.y * w.y;
            acc2[2][0] += a4.z * w.x; acc2[2][1] += a4.z * w.y;
            acc2[3][0] += a4.w * w.x; acc2[3][1] += a4.w * w.y;
        }

        #pragma unroll
        for (int r = 0; r < 4; r++) {
            int row = base + r;
            if (row < NNODES) {
                float2 o = make_float2(acc2[r][0], acc2[r][1]);
                *reinterpret_cast<float2*>(&out[(size_t)row * OUTDIM + lane * 2]) = o;
            }
        }
    }
}

// ---------------------------------------------------------------------------
extern "C" void kernel_launch(void* const* d_in, const int* in_sizes, int n_in,
                              void* d_out, int out_size) {
    const float* x       = (const float*)d_in[0];
    const float* W_in    = (const float*)d_in[1];
    const float* b_in    = (const float*)d_in[2];
    const float* W_self  = (const float*)d_in[3];
    const float* W_neigh = (const float*)d_in[4];
    const float* W_out   = (const float*)d_in[5];
    const float* b_out   = (const float*)d_in[6];
    const int*   ei      = (const int*)d_in[7];
    float* out = (float*)d_out;
    (void)in_sizes; (void)n_in; (void)out_size;

    void *p_agg = nullptr, *p_deg = nullptr;
    cudaGetSymbolAddress(&p_agg, g_agg);
    cudaGetSymbolAddress(&p_deg, g_deg);

    constexpr int SMEM_LIN   = (16384 + 16 * 512) * 4;                   //  96 KB
    constexpr int SMEM_L0    = (16384 + 16384 + 16 * 512) * 4;           // 160 KB
    constexpr int SMEM_L1    = (16384 + 16384 + 8192 + 16 * 512) * 4;    // 192 KB
    cudaFuncSetAttribute(k_lin_in,    cudaFuncAttributeMaxDynamicSharedMemorySize, SMEM_LIN);
    cudaFuncSetAttribute(k_layer<0>,  cudaFuncAttributeMaxDynamicSharedMemorySize, SMEM_L0);
    cudaFuncSetAttribute(k_layer<1>,  cudaFuncAttributeMaxDynamicSharedMemorySize, SMEM_L1);

    const int gemm_grid = (NNODES + 63) / 64;  // 64 rows per 512-thread block

    cudaMemsetAsync(p_deg, 0, NNODES * sizeof(float));
    k_deg<<<592, 512>>>(ei);

    // lin_in + fused top32 -> g_pack
    k_lin_in<<<gemm_grid, 512, SMEM_LIN>>>(x, W_in, b_in, NNODES);

    // layer 0: scatter + (layer GEMM -> top32 -> g_pack)
    cudaMemsetAsync(p_agg, 0, (size_t)NNODES * HIDDIM * sizeof(float));
    k_scatter<<<(NEDGES + 7) / 8, 256>>>(ei);
    k_layer<0><<<gemm_grid, 512, SMEM_L0>>>(W_self, W_neigh, nullptr, nullptr, nullptr);

    // layer 1: scatter + (layer GEMM -> fused lin_out -> d_out)
    cudaMemsetAsync(p_agg, 0, (size_t)NNODES * HIDDIM * sizeof(float));
    k_scatter<<<(NEDGES + 7) / 8, 256>>>(ei);
    k_layer<1><<<gemm_grid, 512, SMEM_L1>>>(W_self + (size_t)128 * 128,
                                            W_neigh + (size_t)128 * 128,
                                            W_out, b_out, out);
}

// round 11
// speedup vs baseline: 1.0726x; 1.0726x over previous
#include <cuda_runtime.h>

// SAGE_69587060130174 — MaxK-GNN forward on GB300 (sm_103a), fp32 SIMT.
// R10 (resubmit, unmeasured due to broker outage): kill latency chains in the
// fused layer kernels — top32 with 4-row ILP, SMEM-broadcast sparse term
// instead of SHFL, conflict-free row-major A-tiles.

static constexpr int NNODES = 50000;
static constexpr int NEDGES = 800000;
static constexpr int HIDDIM = 128;
static constexpr int OUTDIM = 64;
static constexpr int KTOP   = 32;

__device__ float  g_agg[(size_t)NNODES * HIDDIM];   // 25.6 MB
__device__ float2 g_pack[(size_t)NNODES * KTOP];    // 12.8 MB (.x=val,.y=idx bits)
__device__ float  g_deg[NNODES];

// monotonic float<->uint key (order-preserving bijection)
__device__ __forceinline__ unsigned f2key(float x) {
    unsigned k = __float_as_uint(x);
    return (k & 0x80000000u) ? ~k : (k | 0x80000000u);
}
__device__ __forceinline__ float key2f(unsigned k) {
    return __uint_as_float((k & 0x80000000u) ? (k & 0x7fffffffu) : ~k);
}

// ---------------------------------------------------------------------------
// Exact, stable top-32 of FOUR warp-held 128-vectors simultaneously
// (acc[r][q] = row r, col lane*4+q). Per round, the 4 rows' REDUX/ballot
// chains are independent -> 4-way ILP. Tie-break = smallest flat column index
// (strict '>' per-lane scan + lowest-set-lane ballot) — matches jax.lax.top_k.
__device__ __forceinline__ void warp_top32_x4(float acc[4][4], int lane,
                                              int base, int N) {
    const float NEG = __int_as_float(0xff800000);  // -inf
    float2 out[4];
    for (int t = 0; t < 32; t++) {
        #pragma unroll
        for (int r = 0; r < 4; r++) {
            float lm = acc[r][0]; int lq = 0;
            if (acc[r][1] > lm) { lm = acc[r][1]; lq = 1; }
            if (acc[r][2] > lm) { lm = acc[r][2]; lq = 2; }
            if (acc[r][3] > lm) { lm = acc[r][3]; lq = 3; }
            unsigned key  = f2key(lm);
            unsigned wk   = __reduce_max_sync(0xffffffffu, key);
            unsigned ball = __ballot_sync(0xffffffffu, key == wk);
            int srcl = __ffs(ball) - 1;
            int wq   = __shfl_sync(0xffffffffu, lq, srcl);
            if (lane == srcl) {
                if      (lq == 0) acc[r][0] = NEG;
                else if (lq == 1) acc[r][1] = NEG;
                else if (lq == 2) acc[r][2] = NEG;
                else              acc[r][3] = NEG;
            }
            if (lane == t)
                out[r] = make_float2(key2f(wk), __int_as_float((srcl << 2) | wq));
        }
    }
    #pragma unroll
    for (int r = 0; r < 4; r++) {
        int row = base + r;
        if (row < N)
            g_pack[(size_t)row * KTOP + lane] = out[r];  // coalesced 256B/row
    }
}

// ---------------------------------------------------------------------------
__global__ void k_deg(const int* __restrict__ ei) {
    int stride = gridDim.x * blockDim.x;
    for (int e = blockIdx.x * blockDim.x + threadIdx.x; e < NEDGES; e += stride)
        atomicAdd(&g_deg[__ldg(ei + e)], 1.0f);
}

// ---------------------------------------------------------------------------
// lin_in + fused top32: pack = top32(A[N,128] @ W[128,128] + bias).
// A-tile row-major per warp (conflict-free STS.128, broadcast float4 reads).
__global__ __launch_bounds__(512) void k_lin_in(const float* __restrict__ A,
                                                const float* __restrict__ W,
                                                const float* __restrict__ bias,
                                                int N) {
    extern __shared__ float sm[];
    float*  sW = sm;                              // 16384 floats
    float4* sA = (float4*)(sm + 16384);           // 16 warps * 128 float4

    const int tid = threadIdx.x, warp = tid >> 5, lane = tid & 31;

    for (int i = tid; i < 4096; i += blockDim.x)
        ((float4*)sW)[i] = ((const float4*)W)[i];
    __syncthreads();

    const int base = blockIdx.x * 64 + warp * 4;
    float4* myA = sA + warp * 128;

    #pragma unroll
    for (int r = 0; r < 4; r++) {
        int row = base + r;
        float4 av = make_float4(0.f, 0.f, 0.f, 0.f);
        if (row < N) av = ((const float4*)(A + (size_t)row * 128))[lane];
        myA[r * 32 + lane] = av;   // conflict-free
    }
    __syncwarp();

    float acc[4][4];
    #pragma unroll
    for (int q = 0; q < 4; q++) {
        float bv = bias[lane * 4 + q];
        #pragma unroll
        for (int r = 0; r < 4; r++) acc[r][q] = bv;
    }

    #pragma unroll 2
    for (int k4 = 0; k4 < 32; k4++) {
        float4 a0 = myA[k4], a1 = myA[32 + k4], a2 = myA[64 + k4], a3 = myA[96 + k4];
        float a0c[4] = {a0.x, a0.y, a0.z, a0.w};
        float a1c[4] = {a1.x, a1.y, a1.z, a1.w};
        float a2c[4] = {a2.x, a2.y, a2.z, a2.w};
        float a3c[4] = {a3.x, a3.y, a3.z, a3.w};
        #pragma unroll
        for (int u = 0; u < 4; u++) {
            float4 w = *(const float4*)&sW[(k4 * 4 + u) * 128 + lane * 4];
            acc[0][0] += a0c[u] * w.x; acc[0][1] += a0c[u] * w.y; acc[0][2] += a0c[u] * w.z; acc[0][3] += a0c[u] * w.w;
            acc[1][0] += a1c[u] * w.x; acc[1][1] += a1c[u] * w.y; acc[1][2] += a1c[u] * w.z; acc[1][3] += a1c[u] * w.w;
            acc[2][0] += a2c[u] * w.x; acc[2][1] += a2c[u] * w.y; acc[2][2] += a2c[u] * w.z; acc[2][3] += a2c[u] * w.w;
            acc[3][0] += a3c[u] * w.x; acc[3][1] += a3c[u] * w.y; acc[3][2] += a3c[u] * w.z; acc[3][3] += a3c[u] * w.w;
        }
    }

    warp_top32_x4(acc, lane, base, N);
}

// ---------------------------------------------------------------------------
// Edge scatter: one warp per edge; lane handles one of 32 nonzeros of hs[dst]
// (single coalesced float2 load) and atomically adds into agg[src].
__global__ __launch_bounds__(256) void k_scatter(const int* __restrict__ ei) {
    int gw = (blockIdx.x * blockDim.x + threadIdx.x) >> 5;
    if (gw >= NEDGES) return;
    int lane = threadIdx.x & 31;
    int s = __ldg(ei + gw);
    int d = __ldg(ei + NEDGES + gw);
    float2 p = g_pack[(size_t)d * KTOP + lane];
    float* ap = g_agg + (size_t)s * 128;
    atomicAdd(ap + __float_as_int(p.y), p.x);
}

// ---------------------------------------------------------------------------
// Fused layer: t = sparse(pack) @ W_self + (agg/(deg+1e-6)) @ W_neigh.
// MODE 0: pack = top32(t);   MODE 1: out = t @ W_out + b_out (fused lin_out).
// Sparse term reads pack via per-warp SMEM broadcast (no SHFL).
template <int MODE>
__global__ __launch_bounds__(512) void k_layer(const float* __restrict__ Ws,
                                               const float* __restrict__ Wn,
                                               const float* __restrict__ Wo,
                                               const float* __restrict__ bo,
                                               float* __restrict__ out) {
    extern __shared__ float sm[];
    float* sWs = sm;                                   // 16384 floats
    float* sWn = sm + 16384;                           // 16384 floats
    float* sWo = sm + 32768;                           // 8192 floats (MODE 1)
    float* sBase = sm + (MODE ? 40960 : 32768);
    float4* sA  = (float4*)sBase;                      // 16 warps * 128 float4
    float2* sPk = (float2*)(sBase + 8192);             // 16 warps * 128 float2

    const int tid = threadIdx.x, warp = tid >> 5, lane = tid & 31;

    for (int i = tid; i < 4096; i += blockDim.x) {
        ((float4*)sWs)[i] = ((const float4*)Ws)[i];
        ((float4*)sWn)[i] = ((const float4*)Wn)[i];
    }
    if constexpr (MODE == 1) {
        for (int i = tid; i < 2048; i += blockDim.x)
            ((float4*)sWo)[i] = ((const float4*)Wo)[i];
    }
    __syncthreads();

    const int base = blockIdx.x * 64 + warp * 4;
    float4* myA  = sA  + warp * 128;
    float2* myPk = sPk + warp * 128;

    #pragma unroll
    for (int r = 0; r < 4; r++) {
        int row = base + r;
        float4 av = make_float4(0.f, 0.f, 0.f, 0.f);
        float2 p  = make_float2(0.f, __int_as_float(0));
        if (row < NNODES) {
            float inv = 1.0f / (g_deg[row] + 1e-6f);
            float4 a = ((const float4*)(g_agg + (size_t)row * 128))[lane];
            av = make_float4(a.x * inv, a.y * inv, a.z * inv, a.w * inv);
            p  = g_pack[(size_t)row * KTOP + lane];
        }
        myA[r * 32 + lane]  = av;   // conflict-free
        myPk[r * 32 + lane] = p;
    }
    __syncwarp();

    float acc[4][4] = {};

    // sparse self-term: 32 nonzeros/row via uniform SMEM broadcast (no SHFL)
    #pragma unroll 4
    for (int t = 0; t < 32; t++) {
        #pragma unroll
        for (int r = 0; r < 4; r++) {
            float2 p = myPk[r * 32 + t];           // broadcast LDS.64
            int j = __float_as_int(p.y);
            float4 w = *(const float4*)&sWs[j * 128 + lane * 4];
            acc[r][0] += p.x * w.x; acc[r][1] += p.x * w.y;
            acc[r][2] += p.x * w.z; acc[r][3] += p.x * w.w;
        }
    }

    // dense neighbor term (k4-blocked, broadcast row reads)
    #pragma unroll 2
    for (int k4 = 0; k4 < 32; k4++) {
        float4 a0 = myA[k4], a1 = myA[32 + k4], a2 = myA[64 + k4], a3 = myA[96 + k4];
        float a0c[4] = {a0.x, a0.y, a0.z, a0.w};
        float a1c[4] = {a1.x, a1.y, a1.z, a1.w};
        float a2c[4] = {a2.x, a2.y, a2.z, a2.w};
        float a3c[4] = {a3.x, a3.y, a3.z, a3.w};
        #pragma unroll
        for (int u = 0; u < 4; u++) {
            float4 w = *(const float4*)&sWn[(k4 * 4 + u) * 128 + lane * 4];
            acc[0][0] += a0c[u] * w.x; acc[0][1] += a0c[u] * w.y; acc[0][2] += a0c[u] * w.z; acc[0][3] += a0c[u] * w.w;
            acc[1][0] += a1c[u] * w.x; acc[1][1] += a1c[u] * w.y; acc[1][2] += a1c[u] * w.z; acc[1][3] += a1c[u] * w.w;
            acc[2][0] += a2c[u] * w.x; acc[2][1] += a2c[u] * w.y; acc[2][2] += a2c[u] * w.z; acc[2][3] += a2c[u] * w.w;
            acc[3][0] += a3c[u] * w.x; acc[3][1] += a3c[u] * w.y; acc[3][2] += a3c[u] * w.z; acc[3][3] += a3c[u] * w.w;
        }
    }

    if constexpr (MODE == 0) {
        warp_top32_x4(acc, lane, base, NNODES);
    } else {
        // fused lin_out: restage acc as row-major float4 (conflict-free),
        // then the standard CPL=2 GEMM against sWo. Bit-identical to the
        // 2-kernel path (same accumulation order).
        #pragma unroll
        for (int r = 0; r < 4; r++)
            myA[r * 32 + lane] = make_float4(acc[r][0], acc[r][1], acc[r][2], acc[r][3]);
        __syncwarp();

        float acc2[4][2];
        #pragma unroll
        for (int q = 0; q < 2; q++) {
            float bv = bo[lane * 2 + q];
            #pragma unroll
            for (int r = 0; r < 4; r++) acc2[r][q] = bv;
        }

        #pragma unroll 2
        for (int k4 = 0; k4 < 32; k4++) {
            float4 a0 = myA[k4], a1 = myA[32 + k4], a2 = myA[64 + k4], a3 = myA[96 + k4];
            float a0c[4] = {a0.x, a0.y, a0.z, a0.w};
            float a1c[4] = {a1.x, a1.y, a1.z, a1.w};
            float a2c[4] = {a2.x, a2.y, a2.z, a2.w};
            float a3c[4] = {a3.x, a3.y, a3.z, a3.w};
            #pragma unroll
            for (int u = 0; u < 4; u++) {
                float2 w = *(const float2*)&sWo[(k4 * 4 + u) * 64 + lane * 2];
                acc2[0][0] += a0c[u] * w.x; acc2[0][1] += a0c[u] * w.y;
                acc2[1][0] += a1c[u] * w.x; acc2[1][1] += a1c[u] * w.y;
                acc2[2][0] += a2c[u] * w.x; acc2[2][1] += a2c[u] * w.y;
                acc2[3][0] += a3c[u] * w.x; acc2[3][1] += a3c[u] * w.y;
            }
        }

        #pragma unroll
        for (int r = 0; r < 4; r++) {
            int row = base + r;
            if (row < NNODES) {
                float2 o = make_float2(acc2[r][0], acc2[r][1]);
                *reinterpret_cast<float2*>(&out[(size_t)row * OUTDIM + lane * 2]) = o;
            }
        }
    }
}

// ---------------------------------------------------------------------------
extern "C" void kernel_launch(void* const* d_in, const int* in_sizes, int n_in,
                              void* d_out, int out_size) {
    const float* x       = (const float*)d_in[0];
    const float* W_in    = (const float*)d_in[1];
    const float* b_in    = (const float*)d_in[2];
    const float* W_self  = (const float*)d_in[3];
    const float* W_neigh = (const float*)d_in[4];
    const float* W_out   = (const float*)d_in[5];
    const float* b_out   = (const float*)d_in[6];
    const int*   ei      = (const int*)d_in[7];
    float* out = (float*)d_out;
    (void)in_sizes; (void)n_in; (void)out_size;

    void *p_agg = nullptr, *p_deg = nullptr;
    cudaGetSymbolAddress(&p_agg, g_agg);
    cudaGetSymbolAddress(&p_deg, g_deg);

    constexpr int SMEM_LIN = (16384 + 8192) * 4;                         //  96 KB
    constexpr int SMEM_L0  = (16384 + 16384 + 8192 + 4096) * 4;          // 176 KB
    constexpr int SMEM_L1  = (16384 + 16384 + 8192 + 8192 + 4096) * 4;   // 208 KB
    cudaFuncSetAttribute(k_lin_in,   cudaFuncAttributeMaxDynamicSharedMemorySize, SMEM_LIN);
    cudaFuncSetAttribute(k_layer<0>, cudaFuncAttributeMaxDynamicSharedMemorySize, SMEM_L0);
    cudaFuncSetAttribute(k_layer<1>, cudaFuncAttributeMaxDynamicSharedMemorySize, SMEM_L1);

    const int gemm_grid = (NNODES + 63) / 64;  // 64 rows per 512-thread block

    cudaMemsetAsync(p_deg, 0, NNODES * sizeof(float));
    k_deg<<<592, 512>>>(ei);

    k_lin_in<<<gemm_grid, 512, SMEM_LIN>>>(x, W_in, b_in, NNODES);

    cudaMemsetAsync(p_agg, 0, (size_t)NNODES * HIDDIM * sizeof(float));
    k_scatter<<<(NEDGES + 7) / 8, 256>>>(ei);
    k_layer<0><<<gemm_grid, 512, SMEM_L0>>>(W_self, W_neigh, nullptr, nullptr, nullptr);

    cudaMemsetAsync(p_agg, 0, (size_t)NNODES * HIDDIM * sizeof(float));
    k_scatter<<<(NEDGES + 7) / 8, 256>>>(ei);
    k_layer<1><<<gemm_grid, 512, SMEM_L1>>>(W_self + (size_t)128 * 128,
                                            W_neigh + (size_t)128 * 128,
                                            W_out, b_out, out);
}